// round 14
// baseline (speedup 1.0000x reference)
#include <cuda_runtime.h>
#include <math.h>

// Problem constants
#define BB      1024
#define T_TOT   576
#define T_INP   512
#define T_TASK  64
#define HH      100
#define GG      400
#define DF      9
#define BS      8        // batch rows per block
#define NTHREADS 512
#define NBLOCKS  128     // 128 * 8 = 1024 exactly

#define NJ      109      // 9 feature rows (W_x) + 100 hidden rows (W_h)
#define WQSTR   440      // whQ floats per unit: 109*4 + 4 pad (stride%32=24 -> phase-disjoint)
#define HRSTR   108      // hrow/woutT row stride

typedef unsigned long long ull;

struct __align__(16) Smem {
    float whQ[HH * WQSTR];     // whQ[u*440 + j*4 + c]: j<9 -> W_x[j][u+c*100], else W_h[j-9][u+c*100]  176000 B
    float vdup[2][NJ * 16];    // operand vector, duplicated pairs: vdup[j*16 + r*2 + {0,1}] = v_j,r     13952 B
    float hrow[2][BS * HRSTR]; // h row-major (for logits), parity double-buffered                        6912 B
    float woutT[DF * HRSTR];   // W_out^T d-major, k padded to 108 with zeros                             3888 B
    float rawS[2][72];         // raw features, double-buffered (distance-2 prefetch)                      576 B
    float lg[2][72];           // logits, double-buffered                                                  576 B
    float win[81], wtask[81], bin[DF], btask[DF], bout[DF];
};
// ~202.4 KB dynamic smem -> 1 block/SM

__device__ __forceinline__ float sigmoidf_(float x) {
    return __fdividef(1.0f, 1.0f + __expf(-x));
}
__device__ __forceinline__ float tanhf_(float x) {
    return 1.0f - __fdividef(2.0f, 1.0f + __expf(2.0f * x));
}
__device__ __forceinline__ void fma2(ull& acc, ull ab, ull cd) {
    asm("fma.rn.f32x2 %0, %1, %2, %0;" : "+l"(acc) : "l"(ab), "l"(cd));
}
__device__ __forceinline__ ull pack2(float lo, float hi) {
    ull r;
    asm("mov.b64 %0, {%1, %2};" : "=l"(r) : "f"(lo), "f"(hi));
    return r;
}
__device__ __forceinline__ float2 unpack2(ull v) {
    float2 r;
    asm("mov.b64 {%0, %1}, %2;" : "=f"(r.x), "=f"(r.y) : "l"(v));
    return r;
}

__global__ void __launch_bounds__(NTHREADS, 1)
lstm_fused_kernel(const float* __restrict__ input,  // [1024,512,9]
                  const float* __restrict__ task,   // [1024,64,9]
                  const float* __restrict__ W_in,   // [9,9]
                  const float* __restrict__ b_in,   // [9]
                  const float* __restrict__ W_task, // [9,9]
                  const float* __restrict__ b_task, // [9]
                  const float* __restrict__ W_x,    // [9,400]
                  const float* __restrict__ W_h,    // [100,400]
                  const float* __restrict__ b_lstm, // [400]
                  const float* __restrict__ W_out,  // [100,9]
                  const float* __restrict__ b_out,  // [9]
                  float* __restrict__ out)          // [1024,576,9]
{
    extern __shared__ unsigned char smem_raw[];
    Smem* sm = reinterpret_cast<Smem*>(smem_raw);

    const int tid  = threadIdx.x;
    const int row0 = blockIdx.x * BS;

    // ---------------- prologue: stage weights ----------------
    for (int idx = tid; idx < HH * WQSTR; idx += NTHREADS) {
        int u   = idx / WQSTR;
        int rem = idx - u * WQSTR;
        float v = 0.0f;
        if (rem < NJ * 4) {
            int j = rem >> 2, c = rem & 3;
            v = (j < 9) ? W_x[j * GG + u + c * HH]
                        : W_h[(j - 9) * GG + u + c * HH];
        }
        sm->whQ[idx] = v;
    }
    for (int idx = tid; idx < DF * HRSTR; idx += NTHREADS) {
        int d = idx / HRSTR, k = idx - d * HRSTR;
        sm->woutT[idx] = (k < HH) ? W_out[k * DF + d] : 0.0f;
    }
    if (tid < 81) { sm->win[tid] = W_in[tid]; sm->wtask[tid] = W_task[tid]; }
    if (tid < DF) { sm->bin[tid] = b_in[tid]; sm->btask[tid] = b_task[tid]; sm->bout[tid] = b_out[tid]; }
    for (int idx = tid; idx < NJ * 16; idx += NTHREADS) { sm->vdup[0][idx] = 0.0f; sm->vdup[1][idx] = 0.0f; }
    for (int idx = tid; idx < BS * HRSTR; idx += NTHREADS) { sm->hrow[0][idx] = 0.0f; sm->hrow[1][idx] = 0.0f; }

    // GEMM thread identity + persistent registers
    const int u  = tid >> 2;     // unit (valid when tid < 400)
    const int rp = tid & 3;      // row-pair -> rows 2rp, 2rp+1
    ull b01 = 0ull, b23 = 0ull;
    if (tid < GG) {
        b01 = pack2(b_lstm[u], b_lstm[u + HH]);
        b23 = pack2(b_lstm[u + 2 * HH], b_lstm[u + 3 * HH]);
    }
    float cA = 0.0f, cB = 0.0f;  // cell state for rows 2rp, 2rp+1

    __syncthreads();

    // prime: raw(0)->rawS[0], raw(1)->rawS[1], then s(0) dup'd into vdup[0]
    if (tid < 72) {
        sm->rawS[0][tid] = input[(size_t)(row0 + tid / 9) * (T_INP * 9) + (tid % 9)];
    } else if (tid < 144) {
        int j = tid - 72;
        sm->rawS[1][j] = input[((size_t)(row0 + j / 9) * T_INP + 1) * 9 + (j % 9)];
    }
    __syncthreads();
    if (tid < 72) {
        int sr = tid / 9, sf = tid - sr * 9;
        float a = sm->bin[sf];
#pragma unroll
        for (int f = 0; f < 9; f++) a += sm->rawS[0][sr * 9 + f] * sm->win[f * 9 + sf];
        a = fmaxf(a, 0.0f);
        *reinterpret_cast<float2*>(&sm->vdup[0][sf * 16 + sr * 2]) = make_float2(a, a);
    }
    __syncthreads();

    // ---------------- the 576-step scan (ONE barrier per step) ----------------
    for (int t = 0; t < T_TOT; t++) {
        const int rb = t & 1;
        const int wb = 1 - rb;

        // ---- prefetch raw(t+2): issue LDG early (tids 440..511)
        float pv = 0.0f;
        const int pj = tid - 440;
        if (pj >= 0 && pj < 72 && (t + 2) < T_TOT) {
            int tn = t + 2;
            int pr = pj / 9, pc = pj - pr * 9;
            pv = (tn < T_INP)
                     ? input[((size_t)(row0 + pr) * T_INP + tn) * 9 + pc]
                     : task[((size_t)(row0 + pr) * T_TASK + (tn - T_INP)) * 9 + pc];
        }

        if (tid < GG) {
            // ---- fused GEMM + gates: thread owns (unit u, rows 2rp & 2rp+1)
            const float* wq = &sm->whQ[u * WQSTR];
            const float* vd = &sm->vdup[rb][rp * 4];

            ull aA01 = b01, aA23 = b23;   // row 2rp:   (zi,zf), (zg,zo)
            ull aB01 = b01, aB23 = b23;   // row 2rp+1: (zi,zf), (zg,zo)

#pragma unroll
            for (int j = 0; j < NJ; j++) {
                ulonglong2 w2 = *reinterpret_cast<const ulonglong2*>(wq + j * 4);
                ulonglong2 h2 = *reinterpret_cast<const ulonglong2*>(vd + j * 16);
                fma2(aA01, w2.x, h2.x);
                fma2(aA23, w2.y, h2.x);
                fma2(aB01, w2.x, h2.y);
                fma2(aB23, w2.y, h2.y);
            }

            // gates for both rows (all z already in registers)
            float2 pA01 = unpack2(aA01), pA23 = unpack2(aA23);
            float2 pB01 = unpack2(aB01), pB23 = unpack2(aB23);

            float gi = sigmoidf_(pA01.x), gf = sigmoidf_(pA01.y);
            float gg = tanhf_(pA23.x),    go = sigmoidf_(pA23.y);
            cA = gf * cA + gi * gg;
            float hA = go * tanhf_(cA);

            gi = sigmoidf_(pB01.x); gf = sigmoidf_(pB01.y);
            gg = tanhf_(pB23.x);    go = sigmoidf_(pB23.y);
            cB = gf * cB + gi * gg;
            float hB = go * tanhf_(cB);

            // h(t) duplicated into next step's operand buffer + row-major for logits
            *reinterpret_cast<float4*>(&sm->vdup[wb][(9 + u) * 16 + rp * 4]) =
                make_float4(hA, hA, hB, hB);
            sm->hrow[wb][(2 * rp) * HRSTR + u]     = hA;
            sm->hrow[wb][(2 * rp + 1) * HRSTR + u] = hB;
        } else if (tid >= 416) {
            // ---- helpers on warps 13-15 (warp 12 upper lanes idle)
            if (tid < 488) {
                int e  = tid - 416;
                // logits(t-1) from hrow[rb] = h(t-1)
                if (t > 0) {
                    int lr = e / 9, ld = e - lr * 9;
                    const float4* hr4 = reinterpret_cast<const float4*>(&sm->hrow[rb][lr * HRSTR]);
                    const float4* wd4 = reinterpret_cast<const float4*>(&sm->woutT[ld * HRSTR]);
                    float s0 = 0.f, s1 = 0.f, s2 = 0.f, s3 = 0.f;
#pragma unroll
                    for (int kk = 0; kk < 27; kk++) {
                        float4 h4 = hr4[kk];
                        float4 w4 = wd4[kk];
                        s0 += h4.x * w4.x;
                        s1 += h4.y * w4.y;
                        s2 += h4.z * w4.z;
                        s3 += h4.w * w4.w;
                    }
                    sm->lg[wb][e] = sm->bout[ld] + (s0 + s1) + (s2 + s3);
                }
                // encode s(t+1) dup'd into vdup[wb] from rawS[wb]
                if ((t + 1) < T_TOT) {
                    int sr = e / 9, sf = e - sr * 9;
                    const float* rbuf = sm->rawS[wb];
                    const float* We = ((t + 1) < T_INP) ? sm->win : sm->wtask;
                    const float* be = ((t + 1) < T_INP) ? sm->bin : sm->btask;
                    float a = be[sf];
#pragma unroll
                    for (int f = 0; f < 9; f++) a += rbuf[sr * 9 + f] * We[f * 9 + sf];
                    a = fmaxf(a, 0.0f);
                    *reinterpret_cast<float2*>(&sm->vdup[wb][sf * 16 + sr * 2]) = make_float2(a, a);
                }
            } else if (tid < 496 && t >= 2) {
                // softmax + store for step t-2 from lg[rb]
                int r = tid - 488;
                float l[9];
                float m = -1e30f;
#pragma unroll
                for (int d = 0; d < 9; d++) { l[d] = sm->lg[rb][r * 9 + d]; m = fmaxf(m, l[d]); }
                float ssum = 0.0f;
#pragma unroll
                for (int d = 0; d < 9; d++) { l[d] = __expf(l[d] - m); ssum += l[d]; }
                float inv = __fdividef(1.0f, ssum);
                float* op = out + ((size_t)(row0 + r) * T_TOT + (t - 2)) * 9;
#pragma unroll
                for (int d = 0; d < 9; d++) op[d] = l[d] * inv;
            }
        }

        // ---- land prefetched raw(t+2) into rawS[rb]
        if (pj >= 0 && pj < 72 && (t + 2) < T_TOT) sm->rawS[rb][pj] = pv;

        __syncthreads();
    }

    // ---------------- epilogue: logits(575), softmax(574), softmax(575) ----------------
    // h(575) is in hrow[0]; lg[0] holds logits(574).
    if (tid < 72) {
        int lr = tid / 9, ld = tid - lr * 9;
        const float4* hr4 = reinterpret_cast<const float4*>(&sm->hrow[0][lr * HRSTR]);
        const float4* wd4 = reinterpret_cast<const float4*>(&sm->woutT[ld * HRSTR]);
        float s0 = 0.f, s1 = 0.f, s2 = 0.f, s3 = 0.f;
#pragma unroll
        for (int kk = 0; kk < 27; kk++) {
            float4 h4 = hr4[kk];
            float4 w4 = wd4[kk];
            s0 += h4.x * w4.x;
            s1 += h4.y * w4.y;
            s2 += h4.z * w4.z;
            s3 += h4.w * w4.w;
        }
        sm->lg[1][tid] = sm->bout[ld] + (s0 + s1) + (s2 + s3);
    } else if (tid >= 128 && tid < 136) {
        int r = tid - 128;
        float l[9];
        float m = -1e30f;
#pragma unroll
        for (int d = 0; d < 9; d++) { l[d] = sm->lg[0][r * 9 + d]; m = fmaxf(m, l[d]); }
        float ssum = 0.0f;
#pragma unroll
        for (int d = 0; d < 9; d++) { l[d] = __expf(l[d] - m); ssum += l[d]; }
        float inv = __fdividef(1.0f, ssum);
        float* op = out + ((size_t)(row0 + r) * T_TOT + (T_TOT - 2)) * 9;
#pragma unroll
        for (int d = 0; d < 9; d++) op[d] = l[d] * inv;
    }
    __syncthreads();
    if (tid < BS) {
        float l[9];
        float m = -1e30f;
#pragma unroll
        for (int d = 0; d < 9; d++) { l[d] = sm->lg[1][tid * 9 + d]; m = fmaxf(m, l[d]); }
        float ssum = 0.0f;
#pragma unroll
        for (int d = 0; d < 9; d++) { l[d] = __expf(l[d] - m); ssum += l[d]; }
        float inv = __fdividef(1.0f, ssum);
        float* op = out + ((size_t)(row0 + tid) * T_TOT + (T_TOT - 1)) * 9;
#pragma unroll
        for (int d = 0; d < 9; d++) op[d] = l[d] * inv;
    }
}

extern "C" void kernel_launch(void* const* d_in, const int* in_sizes, int n_in,
                              void* d_out, int out_size) {
    const float* input  = (const float*)d_in[0];
    const float* task   = (const float*)d_in[1];
    const float* W_in   = (const float*)d_in[2];
    const float* b_in   = (const float*)d_in[3];
    const float* W_task = (const float*)d_in[4];
    const float* b_task = (const float*)d_in[5];
    const float* W_x    = (const float*)d_in[6];
    const float* W_h    = (const float*)d_in[7];
    const float* b_lstm = (const float*)d_in[8];
    const float* W_out  = (const float*)d_in[9];
    const float* b_out  = (const float*)d_in[10];
    float* out = (float*)d_out;

    cudaFuncSetAttribute(lstm_fused_kernel,
                         cudaFuncAttributeMaxDynamicSharedMemorySize,
                         (int)sizeof(Smem));
    lstm_fused_kernel<<<NBLOCKS, NTHREADS, sizeof(Smem)>>>(
        input, task, W_in, b_in, W_task, b_task,
        W_x, W_h, b_lstm, W_out, b_out, out);
}

// round 15
// speedup vs baseline: 1.0017x; 1.0017x over previous
#include <cuda_runtime.h>
#include <math.h>

// Problem constants
#define BB      1024
#define T_TOT   576
#define T_INP   512
#define T_TASK  64
#define HH      100
#define GG      400
#define DF      9
#define BS      8        // batch rows per block
#define NTHREADS 512
#define NBLOCKS  128     // 128 * 8 = 1024 exactly

#define NJ      109      // 9 feature rows (W_x) + 100 hidden rows (W_h)
#define WQSTR   440      // whQ floats per unit: 109*4 + 4 pad (stride%32=24 -> phase-disjoint)
#define HRSTR   108      // hrow/woutT row stride

typedef unsigned long long ull;

struct __align__(16) Smem {
    float whQ[HH * WQSTR];     // whQ[u*440 + j*4 + c]: j<9 -> W_x[j][u+c*100], else W_h[j-9][u+c*100]  176000 B
    float vdup[2][NJ * 16];    // operand vector, duplicated pairs: vdup[j*16 + r*2 + {0,1}] = v_j,r     13952 B
    float hrow[2][BS * HRSTR]; // h row-major (for logits), parity double-buffered                        6912 B
    float woutT[DF * HRSTR];   // W_out^T d-major, k padded to 108 with zeros                             3888 B
    float rawS[2][72];         // raw features, double-buffered (distance-2 prefetch)                      576 B
    float lg[2][72];           // logits, double-buffered                                                  576 B
    float win[81], wtask[81], bin[DF], btask[DF], bout[DF];
};
// ~202.4 KB dynamic smem -> 1 block/SM

__device__ __forceinline__ float sigmoidf_(float x) {
    return __fdividef(1.0f, 1.0f + __expf(-x));
}
__device__ __forceinline__ float tanhf_(float x) {
    return 1.0f - __fdividef(2.0f, 1.0f + __expf(2.0f * x));
}
__device__ __forceinline__ void fma2(ull& acc, ull ab, ull cd) {
    asm("fma.rn.f32x2 %0, %1, %2, %0;" : "+l"(acc) : "l"(ab), "l"(cd));
}
__device__ __forceinline__ ull pack2(float lo, float hi) {
    ull r;
    asm("mov.b64 %0, {%1, %2};" : "=l"(r) : "f"(lo), "f"(hi));
    return r;
}
__device__ __forceinline__ float2 unpack2(ull v) {
    float2 r;
    asm("mov.b64 {%0, %1}, %2;" : "=f"(r.x), "=f"(r.y) : "l"(v));
    return r;
}

__global__ void __launch_bounds__(NTHREADS, 1)
lstm_fused_kernel(const float* __restrict__ input,  // [1024,512,9]
                  const float* __restrict__ task,   // [1024,64,9]
                  const float* __restrict__ W_in,   // [9,9]
                  const float* __restrict__ b_in,   // [9]
                  const float* __restrict__ W_task, // [9,9]
                  const float* __restrict__ b_task, // [9]
                  const float* __restrict__ W_x,    // [9,400]
                  const float* __restrict__ W_h,    // [100,400]
                  const float* __restrict__ b_lstm, // [400]
                  const float* __restrict__ W_out,  // [100,9]
                  const float* __restrict__ b_out,  // [9]
                  float* __restrict__ out)          // [1024,576,9]
{
    extern __shared__ unsigned char smem_raw[];
    Smem* sm = reinterpret_cast<Smem*>(smem_raw);

    const int tid  = threadIdx.x;
    const int row0 = blockIdx.x * BS;

    // ---------------- prologue: stage weights ----------------
    for (int idx = tid; idx < HH * WQSTR; idx += NTHREADS) {
        int u   = idx / WQSTR;
        int rem = idx - u * WQSTR;
        float v = 0.0f;
        if (rem < NJ * 4) {
            int j = rem >> 2, c = rem & 3;
            v = (j < 9) ? W_x[j * GG + u + c * HH]
                        : W_h[(j - 9) * GG + u + c * HH];
        }
        sm->whQ[idx] = v;
    }
    for (int idx = tid; idx < DF * HRSTR; idx += NTHREADS) {
        int d = idx / HRSTR, k = idx - d * HRSTR;
        sm->woutT[idx] = (k < HH) ? W_out[k * DF + d] : 0.0f;
    }
    if (tid < 81) { sm->win[tid] = W_in[tid]; sm->wtask[tid] = W_task[tid]; }
    if (tid < DF) { sm->bin[tid] = b_in[tid]; sm->btask[tid] = b_task[tid]; sm->bout[tid] = b_out[tid]; }
    for (int idx = tid; idx < NJ * 16; idx += NTHREADS) { sm->vdup[0][idx] = 0.0f; sm->vdup[1][idx] = 0.0f; }
    for (int idx = tid; idx < BS * HRSTR; idx += NTHREADS) { sm->hrow[0][idx] = 0.0f; sm->hrow[1][idx] = 0.0f; }

    // GEMM thread identity + persistent registers
    const int u  = tid >> 2;     // unit (valid when tid < 400)
    const int rp = tid & 3;      // row-pair -> rows 2rp, 2rp+1
    ull b01 = 0ull, b23 = 0ull;
    if (tid < GG) {
        b01 = pack2(b_lstm[u], b_lstm[u + HH]);
        b23 = pack2(b_lstm[u + 2 * HH], b_lstm[u + 3 * HH]);
    }
    float cA = 0.0f, cB = 0.0f;  // cell state for rows 2rp, 2rp+1

    __syncthreads();

    // prime: raw(0)->rawS[0], raw(1)->rawS[1], then s(0) dup'd into vdup[0]
    if (tid < 72) {
        sm->rawS[0][tid] = input[(size_t)(row0 + tid / 9) * (T_INP * 9) + (tid % 9)];
    } else if (tid < 144) {
        int j = tid - 72;
        sm->rawS[1][j] = input[((size_t)(row0 + j / 9) * T_INP + 1) * 9 + (j % 9)];
    }
    __syncthreads();
    if (tid < 72) {
        int sr = tid / 9, sf = tid - sr * 9;
        float a = sm->bin[sf];
#pragma unroll
        for (int f = 0; f < 9; f++) a += sm->rawS[0][sr * 9 + f] * sm->win[f * 9 + sf];
        a = fmaxf(a, 0.0f);
        *reinterpret_cast<float2*>(&sm->vdup[0][sf * 16 + sr * 2]) = make_float2(a, a);
    }
    __syncthreads();

    // ---------------- the 576-step scan (ONE barrier per step) ----------------
    for (int t = 0; t < T_TOT; t++) {
        const int rb = t & 1;
        const int wb = 1 - rb;

        // ---- prefetch raw(t+2): issue LDG early (tids 440..511)
        float pv = 0.0f;
        const int pj = tid - 440;
        if (pj >= 0 && pj < 72 && (t + 2) < T_TOT) {
            int tn = t + 2;
            int pr = pj / 9, pc = pj - pr * 9;
            pv = (tn < T_INP)
                     ? input[((size_t)(row0 + pr) * T_INP + tn) * 9 + pc]
                     : task[((size_t)(row0 + pr) * T_TASK + (tn - T_INP)) * 9 + pc];
        }

        if (tid < GG) {
            // ---- fused GEMM + gates: thread owns (unit u, rows 2rp & 2rp+1)
            const float* wq = &sm->whQ[u * WQSTR];
            const float* vd = &sm->vdup[rb][rp * 4];

            ull aA01 = b01, aA23 = b23;   // row 2rp:   (zi,zf), (zg,zo)
            ull aB01 = b01, aB23 = b23;   // row 2rp+1: (zi,zf), (zg,zo)

#pragma unroll
            for (int j = 0; j < NJ; j++) {
                ulonglong2 w2 = *reinterpret_cast<const ulonglong2*>(wq + j * 4);
                ulonglong2 h2 = *reinterpret_cast<const ulonglong2*>(vd + j * 16);
                fma2(aA01, w2.x, h2.x);
                fma2(aA23, w2.y, h2.x);
                fma2(aB01, w2.x, h2.y);
                fma2(aB23, w2.y, h2.y);
            }

            // gates for both rows (all z already in registers)
            float2 pA01 = unpack2(aA01), pA23 = unpack2(aA23);
            float2 pB01 = unpack2(aB01), pB23 = unpack2(aB23);

            float gi = sigmoidf_(pA01.x), gf = sigmoidf_(pA01.y);
            float gg = tanhf_(pA23.x),    go = sigmoidf_(pA23.y);
            cA = gf * cA + gi * gg;
            float hA = go * tanhf_(cA);

            gi = sigmoidf_(pB01.x); gf = sigmoidf_(pB01.y);
            gg = tanhf_(pB23.x);    go = sigmoidf_(pB23.y);
            cB = gf * cB + gi * gg;
            float hB = go * tanhf_(cB);

            // h(t) duplicated into next step's operand buffer + row-major for logits
            *reinterpret_cast<float4*>(&sm->vdup[wb][(9 + u) * 16 + rp * 4]) =
                make_float4(hA, hA, hB, hB);
            sm->hrow[wb][(2 * rp) * HRSTR + u]     = hA;
            sm->hrow[wb][(2 * rp + 1) * HRSTR + u] = hB;
        } else if (tid >= 416) {
            // ---- helpers on warps 13-15 (warp 12 upper lanes idle)
            if (tid < 488) {
                int e  = tid - 416;
                // logits(t-1) from hrow[rb] = h(t-1)
                if (t > 0) {
                    int lr = e / 9, ld = e - lr * 9;
                    const float4* hr4 = reinterpret_cast<const float4*>(&sm->hrow[rb][lr * HRSTR]);
                    const float4* wd4 = reinterpret_cast<const float4*>(&sm->woutT[ld * HRSTR]);
                    float s0 = 0.f, s1 = 0.f, s2 = 0.f, s3 = 0.f;
#pragma unroll
                    for (int kk = 0; kk < 27; kk++) {
                        float4 h4 = hr4[kk];
                        float4 w4 = wd4[kk];
                        s0 += h4.x * w4.x;
                        s1 += h4.y * w4.y;
                        s2 += h4.z * w4.z;
                        s3 += h4.w * w4.w;
                    }
                    sm->lg[wb][e] = sm->bout[ld] + (s0 + s1) + (s2 + s3);
                }
                // encode s(t+1) dup'd into vdup[wb] from rawS[wb]
                if ((t + 1) < T_TOT) {
                    int sr = e / 9, sf = e - sr * 9;
                    const float* rbuf = sm->rawS[wb];
                    const float* We = ((t + 1) < T_INP) ? sm->win : sm->wtask;
                    const float* be = ((t + 1) < T_INP) ? sm->bin : sm->btask;
                    float a = be[sf];
#pragma unroll
                    for (int f = 0; f < 9; f++) a += rbuf[sr * 9 + f] * We[f * 9 + sf];
                    a = fmaxf(a, 0.0f);
                    *reinterpret_cast<float2*>(&sm->vdup[wb][sf * 16 + sr * 2]) = make_float2(a, a);
                }
            } else if (tid < 496 && t >= 2) {
                // softmax + store for step t-2 from lg[rb]
                int r = tid - 488;
                float l[9];
                float m = -1e30f;
#pragma unroll
                for (int d = 0; d < 9; d++) { l[d] = sm->lg[rb][r * 9 + d]; m = fmaxf(m, l[d]); }
                float ssum = 0.0f;
#pragma unroll
                for (int d = 0; d < 9; d++) { l[d] = __expf(l[d] - m); ssum += l[d]; }
                float inv = __fdividef(1.0f, ssum);
                float* op = out + ((size_t)(row0 + r) * T_TOT + (t - 2)) * 9;
#pragma unroll
                for (int d = 0; d < 9; d++) op[d] = l[d] * inv;
            }
        }

        // ---- land prefetched raw(t+2) into rawS[rb]
        if (pj >= 0 && pj < 72 && (t + 2) < T_TOT) sm->rawS[rb][pj] = pv;

        __syncthreads();
    }

    // ---------------- epilogue: logits(575), softmax(574), softmax(575) ----------------
    // h(575) is in hrow[0]; lg[0] holds logits(574).
    if (tid < 72) {
        int lr = tid / 9, ld = tid - lr * 9;
        const float4* hr4 = reinterpret_cast<const float4*>(&sm->hrow[0][lr * HRSTR]);
        const float4* wd4 = reinterpret_cast<const float4*>(&sm->woutT[ld * HRSTR]);
        float s0 = 0.f, s1 = 0.f, s2 = 0.f, s3 = 0.f;
#pragma unroll
        for (int kk = 0; kk < 27; kk++) {
            float4 h4 = hr4[kk];
            float4 w4 = wd4[kk];
            s0 += h4.x * w4.x;
            s1 += h4.y * w4.y;
            s2 += h4.z * w4.z;
            s3 += h4.w * w4.w;
        }
        sm->lg[1][tid] = sm->bout[ld] + (s0 + s1) + (s2 + s3);
    } else if (tid >= 128 && tid < 136) {
        int r = tid - 128;
        float l[9];
        float m = -1e30f;
#pragma unroll
        for (int d = 0; d < 9; d++) { l[d] = sm->lg[0][r * 9 + d]; m = fmaxf(m, l[d]); }
        float ssum = 0.0f;
#pragma unroll
        for (int d = 0; d < 9; d++) { l[d] = __expf(l[d] - m); ssum += l[d]; }
        float inv = __fdividef(1.0f, ssum);
        float* op = out + ((size_t)(row0 + r) * T_TOT + (T_TOT - 2)) * 9;
#pragma unroll
        for (int d = 0; d < 9; d++) op[d] = l[d] * inv;
    }
    __syncthreads();
    if (tid < BS) {
        float l[9];
        float m = -1e30f;
#pragma unroll
        for (int d = 0; d < 9; d++) { l[d] = sm->lg[1][tid * 9 + d]; m = fmaxf(m, l[d]); }
        float ssum = 0.0f;
#pragma unroll
        for (int d = 0; d < 9; d++) { l[d] = __expf(l[d] - m); ssum += l[d]; }
        float inv = __fdividef(1.0f, ssum);
        float* op = out + ((size_t)(row0 + tid) * T_TOT + (T_TOT - 1)) * 9;
#pragma unroll
        for (int d = 0; d < 9; d++) op[d] = l[d] * inv;
    }
}

extern "C" void kernel_launch(void* const* d_in, const int* in_sizes, int n_in,
                              void* d_out, int out_size) {
    const float* input  = (const float*)d_in[0];
    const float* task   = (const float*)d_in[1];
    const float* W_in   = (const float*)d_in[2];
    const float* b_in   = (const float*)d_in[3];
    const float* W_task = (const float*)d_in[4];
    const float* b_task = (const float*)d_in[5];
    const float* W_x    = (const float*)d_in[6];
    const float* W_h    = (const float*)d_in[7];
    const float* b_lstm = (const float*)d_in[8];
    const float* W_out  = (const float*)d_in[9];
    const float* b_out  = (const float*)d_in[10];
    float* out = (float*)d_out;

    cudaFuncSetAttribute(lstm_fused_kernel,
                         cudaFuncAttributeMaxDynamicSharedMemorySize,
                         (int)sizeof(Smem));
    lstm_fused_kernel<<<NBLOCKS, NTHREADS, sizeof(Smem)>>>(
        input, task, W_in, b_in, W_task, b_task,
        W_x, W_h, b_lstm, W_out, b_out, out);
}